// round 14
// baseline (speedup 1.0000x reference)
#include <cuda_runtime.h>
#include <cstdint>

#define BB      8
#define CTOT    256
#define HH      96
#define WW      128
#define THREADS 288                // 9 warps, one dy each
#define CHS     (HH*WW)            // channel stride (floats)
#define CHS4    (CHS/4)            // channel stride (float4)

typedef unsigned long long ull;

__device__ float4 g_zero4 = {0.f, 0.f, 0.f, 0.f};   // OOB target (stride-0 lanes)

__device__ __forceinline__ ull pk(float lo, float hi) {
    ull r;
    asm("mov.b64 %0, {%1,%2};" : "=l"(r) : "f"(lo), "f"(hi));
    return r;
}
__device__ __forceinline__ float2 upk(ull v) {
    float2 f;
    asm("mov.b64 {%0,%1}, %2;" : "=f"(f.x), "=f"(f.y) : "l"(v));
    return f;
}
__device__ __forceinline__ void ffma2(ull& d, ull a, ull b) {
    asm("fma.rn.f32x2 %0, %1, %2, %0;" : "+l"(d) : "l"(a), "l"(b));
}

// One channel: window f[0..11] = qL | m | qR, 11 packs, 18 packed FMAs.
__device__ __forceinline__ void compute_channel(float4 a, float4 qL, float4 m,
                                                float4 qR, ull acc[9][2])
{
    ull A0 = pk(a.x, a.y);
    ull A1 = pk(a.z, a.w);

    ull E[6], O[5];
    E[0] = pk(qL.x, qL.y); E[1] = pk(qL.z, qL.w);
    E[2] = pk(m.x,  m.y ); E[3] = pk(m.z,  m.w );
    E[4] = pk(qR.x, qR.y); E[5] = pk(qR.z, qR.w);
    O[0] = pk(qL.y, qL.z); O[1] = pk(qL.w, m.x );
    O[2] = pk(m.y,  m.z ); O[3] = pk(m.w,  qR.x);
    O[4] = pk(qR.y, qR.z);

#pragma unroll
    for (int d = 0; d < 9; d++) {
        ull b0 = (d & 1) ? O[(d >> 1)]     : E[(d >> 1)];
        ull b1 = (d & 1) ? O[(d >> 1) + 1] : E[(d >> 1) + 1];
        ffma2(acc[d][0], A0, b0);
        ffma2(acc[d][1], A1, b1);
    }
}

__global__ void __launch_bounds__(THREADS, 2)
corr_kernel(const float* __restrict__ in1, const float* __restrict__ in2,
            float* __restrict__ out)
{
    const int tid  = threadIdx.x;
    const int warp = tid >> 5;         // dy 0..8
    const int lane = tid & 31;
    const int x0   = lane << 2;        // 4 px per lane

    const int bx = blockIdx.x;
    const int b  = bx / HH;
    const int h0 = bx - b * HH;        // output row

    const int hB = h0 + warp - 4;      // this warp's in2 source row
    const bool rowOK = (hB >= 0) && (hB < HH);   // warp-uniform

    ull acc[9][2];
#pragma unroll
    for (int d = 0; d < 9; d++) { acc[d][0] = 0ull; acc[d][1] = 0ull; }

    if (rowOK) {
        const float4* pA = (const float4*)(in1 + (size_t)(b * CTOT) * CHS + h0 * WW + x0);
        const float*  base = in2 + (size_t)(b * CTOT) * CHS + hB * WW + x0;

        // M: deep (distance-4) prefetch stream. L/R/A: just-in-time L1 hits
        // (their lines were fetched by M's prefetch / neighbor warps).
        const bool okL = (lane > 0), okR = (lane < 31);
        const float4* pM = (const float4*)base;
        const float4* pL = okL ? (const float4*)(base - 4) : &g_zero4;
        const float4* pR = okR ? (const float4*)(base + 4) : &g_zero4;
        const size_t sL = okL ? (size_t)CHS4 : 0;
        const size_t sR = okR ? (size_t)CHS4 : 0;

        float4 M0 = __ldg(pM);
        float4 M1 = __ldg(pM + CHS4);
        float4 M2 = __ldg(pM + 2 * CHS4);
        float4 M3 = __ldg(pM + 3 * CHS4);
        pM += 4 * CHS4;

#pragma unroll 2
        for (int c = 0; c < CTOT - 4; c += 2) {
            float4 M4 = __ldg(pM);
            float4 M5 = __ldg(pM + CHS4);
            pM += 2 * CHS4;

            // channel c (JIT loads hit L1)
            float4 L0 = __ldg(pL);
            float4 R0 = __ldg(pR);
            float4 a0 = __ldg(pA);
            pL += sL; pR += sR; pA += CHS4;
            compute_channel(a0, L0, M0, R0, acc);

            // channel c+1
            float4 L1 = __ldg(pL);
            float4 R1 = __ldg(pR);
            float4 a1 = __ldg(pA);
            pL += sL; pR += sR; pA += CHS4;
            compute_channel(a1, L1, M1, R1, acc);

            M0 = M2; M1 = M3; M2 = M4; M3 = M5;
        }

        // Tail: last 4 channels from slots M0..M3
#pragma unroll
        for (int t = 0; t < 4; t++) {
            float4 Lt = __ldg(pL);
            float4 Rt = __ldg(pR);
            float4 at = __ldg(pA);
            pL += sL; pR += sR; pA += CHS4;
            float4 Mt = (t == 0) ? M0 : (t == 1) ? M1 : (t == 2) ? M2 : M3;
            compute_channel(at, Lt, Mt, Rt, acc);
        }
    }

    // Epilogue: out[b, warp*9+d, h0, x0..x0+3] = acc / 256  (zeros when !rowOK)
    const float inv = 1.0f / 256.0f;
#pragma unroll
    for (int d = 0; d < 9; d++) {
        const int n = warp * 9 + d;
        float* op = out + ((size_t)((b * 81 + n) * HH + h0)) * WW + x0;
        float2 u0 = upk(acc[d][0]);
        float2 u1 = upk(acc[d][1]);
        *(float4*)op = make_float4(u0.x * inv, u0.y * inv, u1.x * inv, u1.y * inv);
    }
}

extern "C" void kernel_launch(void* const* d_in, const int* in_sizes, int n_in,
                              void* d_out, int out_size)
{
    const float* in1 = (const float*)d_in[0];
    const float* in2 = (const float*)d_in[1];
    float* out = (float*)d_out;

    corr_kernel<<<BB * HH, THREADS>>>(in1, in2, out);
}

// round 15
// speedup vs baseline: 1.2108x; 1.2108x over previous
#include <cuda_runtime.h>
#include <cstdint>

#define BB      8
#define CTOT    256
#define HH      96
#define WW      128
#define CK      16                 // channels per chunk (2 k8 steps)
#define NCH     (CTOT/CK)          // 16
#define THREADS 288                // 9 warps, one dy each
#define CHS     (HH*WW)

// smem strides (bytes), padded for conflict-free fragment loads
#define SA_K       160                         // A: per-channel row (32 floats used)
#define SA_BYTES   (CK*SA_K)                   // 2560
#define SB_K       224                         // B: per-channel row (48 floats used)
#define SB_DY      (CK*SB_K)                   // 3584
#define SB_BYTES   (9*SB_DY)                   // 32256
#define BUF_BYTES  (SA_BYTES+SB_BYTES)         // 34816
#define SMEM_TOTAL (2*BUF_BYTES)               // 69632 -> 3 blocks/SM

#define NBCH       1728                        // B 16B-chunks per buffer (9*16*12)
#define NTOT       (128+NBCH)                  // +A chunks (16*8)

__device__ __forceinline__ void cpa16(uint32_t dst, const float* src) {
    asm volatile("cp.async.cg.shared.global [%0], [%1], 16;" :: "r"(dst), "l"(src));
}
__device__ __forceinline__ void sts_zero16(uint32_t addr) {
    asm volatile("st.shared.v4.b32 [%0], {%1,%1,%1,%1};" :: "r"(addr), "r"(0) : "memory");
}
__device__ __forceinline__ float lds32(uint32_t a) {
    float v;
    asm volatile("ld.shared.f32 %0, [%1];" : "=f"(v) : "r"(a));
    return v;
}
__device__ __forceinline__ uint32_t tf32c(float x) {
    uint32_t r;
    asm("cvt.rna.tf32.f32 %0, %1;" : "=r"(r) : "f"(x));
    return r;
}
__device__ __forceinline__ void mma8(float* d, const uint32_t* a, const uint32_t* b) {
    asm volatile(
        "mma.sync.aligned.m16n8k8.row.col.f32.tf32.tf32.f32 "
        "{%0,%1,%2,%3}, {%4,%5,%6,%7}, {%8,%9}, {%0,%1,%2,%3};"
        : "+f"(d[0]), "+f"(d[1]), "+f"(d[2]), "+f"(d[3])
        : "r"(a[0]), "r"(a[1]), "r"(a[2]), "r"(a[3]), "r"(b[0]), "r"(b[1]));
}

// Block-wide loader: A tile (CK x 32 floats) + B tiles (9 dy x CK x 48 floats).
__device__ __forceinline__ void load_chunk(uint32_t buf,
                                           const float* __restrict__ in1,
                                           const float* __restrict__ in2,
                                           int b, int c0, int h, int X0, int tid)
{
    for (int idx = tid; idx < NTOT; idx += THREADS) {
        if (idx < 128) {                       // A: k = idx>>3, i = idx&7
            int k = idx >> 3, i = idx & 7;
            const float* src = in1 + ((size_t)((b * CTOT + c0 + k) * HH + h)) * WW
                             + X0 + i * 4;
            cpa16(buf + k * SA_K + i * 16, src);
        } else {                               // B: 12 16B-chunks per (dy,k) row
            int t = idx - 128;
            int dyk = t / 12, i = t - dyk * 12;
            int dy = dyk >> 4, k = dyk & 15;
            int hB = h + dy - 4;
            int col = X0 - 8 + i * 4;
            if (hB >= 0 && hB < HH && col >= 0 && col <= WW - 4) {
                const float* src = in2 + ((size_t)((b * CTOT + c0 + k) * HH + hB)) * WW + col;
                cpa16(buf + SA_BYTES + dy * SB_DY + k * SB_K + i * 16, src);
            }
        }
    }
    asm volatile("cp.async.commit_group;" ::: "memory");
}

__global__ void __launch_bounds__(THREADS, 3)
corr_kernel(const float* __restrict__ in1, const float* __restrict__ in2,
            float* __restrict__ out)
{
    extern __shared__ char smem[];
    const uint32_t smem32 = (uint32_t)__cvta_generic_to_shared(smem);

    const int tid  = threadIdx.x;
    const int warp = tid >> 5;         // dy 0..8
    const int lane = tid & 31;
    const int gid  = lane >> 2;        // mma groupID (0..7)
    const int tig  = lane & 3;         // thread-in-group (0..3)

    const int bx  = blockIdx.x;
    const int b   = bx / 384;
    const int rem = bx - b * 384;
    const int h   = rem >> 2;
    const int X0  = (rem & 3) * 32;

    // Pre-zero OOB B chunks in BOTH buffers (never overwritten by cp.async).
    for (int idx = tid; idx < NBCH; idx += THREADS) {
        int dyk = idx / 12, i = idx - dyk * 12;
        int dy = dyk >> 4, k = dyk & 15;
        int hB = h + dy - 4;
        int col = X0 - 8 + i * 4;
        if (!(hB >= 0 && hB < HH && col >= 0 && col <= WW - 4)) {
            uint32_t off = SA_BYTES + dy * SB_DY + k * SB_K + i * 16;
            sts_zero16(smem32 + off);
            sts_zero16(smem32 + BUF_BYTES + off);
        }
    }
    __syncthreads();

    float acc[6][4];                   // (T=0: nb0,1,2) (T=1: nb2,3,4)
#pragma unroll
    for (int e = 0; e < 6; e++)
#pragma unroll
        for (int j = 0; j < 4; j++) acc[e][j] = 0.f;

    load_chunk(smem32, in1, in2, b, 0, h, X0, tid);

    for (int kc = 0; kc < NCH; kc++) {
        if (kc + 1 < NCH) {
            load_chunk(smem32 + (uint32_t)(((kc + 1) & 1) * BUF_BYTES),
                       in1, in2, b, (kc + 1) * CK, h, X0, tid);
            asm volatile("cp.async.wait_group 1;" ::: "memory");
        } else {
            asm volatile("cp.async.wait_group 0;" ::: "memory");
        }
        __syncthreads();

        const uint32_t buf = smem32 + (uint32_t)((kc & 1) * BUF_BYTES);
        const uint32_t sB  = buf + SA_BYTES + warp * SB_DY;
#pragma unroll
        for (int s = 0; s < 2; s++) {
            // A fragments: two m16 tiles, row-major m16k8
            uint32_t a[2][4];
            const uint32_t ak = buf + (s * 8 + tig) * SA_K;
#pragma unroll
            for (int T = 0; T < 2; T++) {
                uint32_t base = ak + (uint32_t)((16 * T + gid) * 4);
                a[T][0] = tf32c(lds32(base));
                a[T][1] = tf32c(lds32(base + 32));
                a[T][2] = tf32c(lds32(base + 4 * SA_K));
                a[T][3] = tf32c(lds32(base + 4 * SA_K + 32));
            }
            // B fragments: 5 n-blocks (col-major k8n8), col' = 4 + 8*nb + gid
            uint32_t bf[5][2];
            const uint32_t bk = sB + (s * 8 + tig) * SB_K + (uint32_t)((4 + gid) * 4);
#pragma unroll
            for (int nb = 0; nb < 5; nb++) {
                bf[nb][0] = tf32c(lds32(bk + nb * 32));
                bf[nb][1] = tf32c(lds32(bk + nb * 32 + 4 * SB_K));
            }
            mma8(acc[0], a[0], bf[0]);
            mma8(acc[1], a[0], bf[1]);
            mma8(acc[2], a[0], bf[2]);
            mma8(acc[3], a[1], bf[2]);
            mma8(acc[4], a[1], bf[3]);
            mma8(acc[5], a[1], bf[4]);
        }
        __syncthreads();
    }

    // Epilogue: acc entry (row,n) -> x = X0+16T+row, d = 8*nb + n - 16T - row
    const float inv = 1.0f / 256.0f;
#pragma unroll
    for (int e = 0; e < 6; e++) {
        const int T  = (e < 3) ? 0 : 1;
        const int nb = (e < 3) ? e : e - 1;
#pragma unroll
        for (int j = 0; j < 4; j++) {
            int row = gid + ((j >> 1) << 3);
            int n   = 2 * tig + (j & 1);
            int d   = 8 * nb + n - 16 * T - row;
            if (d >= 0 && d <= 8) {
                int x = X0 + 16 * T + row;
                out[((size_t)((b * 81 + warp * 9 + d)) * HH + h) * WW + x] = acc[e][j] * inv;
            }
        }
    }
}

extern "C" void kernel_launch(void* const* d_in, const int* in_sizes, int n_in,
                              void* d_out, int out_size)
{
    const float* in1 = (const float*)d_in[0];
    const float* in2 = (const float*)d_in[1];
    float* out = (float*)d_out;

    cudaFuncSetAttribute(corr_kernel, cudaFuncAttributeMaxDynamicSharedMemorySize, SMEM_TOTAL);
    corr_kernel<<<BB * HH * 4, THREADS, SMEM_TOTAL>>>(in1, in2, out);
}